// round 8
// baseline (speedup 1.0000x reference)
#include <cuda_runtime.h>

// exp(Q*t) for 2,097,152 independent 4x4 fp32 matrices.
// Packed f32x2 + Paterson-Stockmeyer degree-8 Taylor (theta=1) + squaring.
// R8: R6 baseline (1 matrix/thread, 256 TPB, streaming hints) with the
// broadcast operand synthesized PER ROW inside the matmul instead of being
// materialized as 16x u64 arrays -> peak live set shrinks, and
// __launch_bounds__(256,5) forces a 48-reg target = 5 CTAs/SM (62.5% occ,
// up from 40%). Same FMA-pipe op count; goal is issue-rate via warp count.

#define SEQ_SHIFT 15
#define NMAT (64 * 32768)
#define TPB 256

typedef unsigned long long u64;

__device__ __forceinline__ u64 pack2(float lo, float hi) {
    u64 r; asm("mov.b64 %0, {%1, %2};" : "=l"(r) : "f"(lo), "f"(hi)); return r;
}
__device__ __forceinline__ void unpack2(u64 v, float& lo, float& hi) {
    asm("mov.b64 {%0, %1}, %2;" : "=f"(lo), "=f"(hi) : "l"(v));
}
__device__ __forceinline__ u64 fma2(u64 a, u64 b, u64 c) {
    u64 d; asm("fma.rn.f32x2 %0, %1, %2, %3;" : "=l"(d) : "l"(a), "l"(b), "l"(c)); return d;
}
__device__ __forceinline__ u64 mul2(u64 a, u64 b) {
    u64 d; asm("mul.rn.f32x2 %0, %1, %2;" : "=l"(d) : "l"(a), "l"(b)); return d;
}
__device__ __forceinline__ u64 add2(u64 a, u64 b) {
    u64 d; asm("add.rn.f32x2 %0, %1, %2;" : "=l"(d) : "l"(a), "l"(b)); return d;
}
__device__ __forceinline__ u64 abs2(u64 v) { return v & 0x7FFFFFFF7FFFFFFFull; }

// C = A*B. BOTH operands as 8 packed row-pairs; the 4 broadcast values for
// row i of A are synthesized on the fly (live range = one row, not 16 u64).
__device__ __forceinline__ void mm4p_rp(const u64* __restrict__ Arp,
                                        const u64* __restrict__ B,
                                        u64* __restrict__ C) {
#pragma unroll
    for (int i = 0; i < 4; ++i) {
        float a0, a1, a2, a3;
        unpack2(Arp[2 * i],     a0, a1);
        unpack2(Arp[2 * i + 1], a2, a3);
        const u64 p0 = pack2(a0, a0), p1 = pack2(a1, a1);
        const u64 p2 = pack2(a2, a2), p3 = pack2(a3, a3);
#pragma unroll
        for (int jp = 0; jp < 2; ++jp) {
            u64 acc = mul2(p0, B[0 * 2 + jp]);
            acc = fma2(p1, B[1 * 2 + jp], acc);
            acc = fma2(p2, B[2 * 2 + jp], acc);
            acc = fma2(p3, B[3 * 2 + jp], acc);
            C[i * 2 + jp] = acc;
        }
    }
}

// C = A*B + D, same row-pair A form, additive matrix fused into acc init.
__device__ __forceinline__ void mm4p_rp_acc(const u64* __restrict__ Arp,
                                            const u64* __restrict__ B,
                                            const u64* __restrict__ D,
                                            u64* __restrict__ C) {
#pragma unroll
    for (int i = 0; i < 4; ++i) {
        float a0, a1, a2, a3;
        unpack2(Arp[2 * i],     a0, a1);
        unpack2(Arp[2 * i + 1], a2, a3);
        const u64 p0 = pack2(a0, a0), p1 = pack2(a1, a1);
        const u64 p2 = pack2(a2, a2), p3 = pack2(a3, a3);
#pragma unroll
        for (int jp = 0; jp < 2; ++jp) {
            u64 acc = fma2(p0, B[0 * 2 + jp], D[i * 2 + jp]);
            acc = fma2(p1, B[1 * 2 + jp], acc);
            acc = fma2(p2, B[2 * 2 + jp], acc);
            acc = fma2(p3, B[3 * 2 + jp], acc);
            C[i * 2 + jp] = acc;
        }
    }
}

__global__ __launch_bounds__(TPB, 5)
void expm44_kernel(const float* __restrict__ rate,   // [NMAT, 16]
                   const float* __restrict__ time,   // [64]
                   float* __restrict__ out)          // [NMAT, 16]
{
    const int idx = blockIdx.x * TPB + threadIdx.x;   // grid is exact

    const float t = __ldg(time + (idx >> SEQ_SHIFT));

    // Load 16 floats as 8 packed f32x2 row-pairs (4x LDG.128, streaming).
    const ulonglong2* ap = reinterpret_cast<const ulonglong2*>(rate) + (size_t)idx * 4;
    ulonglong2 l0 = __ldcs(ap + 0);
    ulonglong2 l1 = __ldcs(ap + 1);
    ulonglong2 l2 = __ldcs(ap + 2);
    ulonglong2 l3 = __ldcs(ap + 3);
    u64 Xp[8] = { l0.x, l0.y, l1.x, l1.y, l2.x, l2.y, l3.x, l3.y };

    // inf-norm(A) * t
    u64 q0 = add2(abs2(Xp[0]), abs2(Xp[1]));
    u64 q1 = add2(abs2(Xp[2]), abs2(Xp[3]));
    u64 q2 = add2(abs2(Xp[4]), abs2(Xp[5]));
    u64 q3 = add2(abs2(Xp[6]), abs2(Xp[7]));
    float a0, b0, a1, b1, a2, b2, a3, b3;
    unpack2(q0, a0, b0); unpack2(q1, a1, b1);
    unpack2(q2, a2, b2); unpack2(q3, a3, b3);
    const float nrm = fmaxf(fmaxf(a0 + b0, a1 + b1), fmaxf(a2 + b2, a3 + b3)) * t;

    // s ~ ceil(log2(nrm)) via exponent extraction; clamp [0,16]; warp-max.
    int s = (int)(__float_as_uint(nrm) >> 23) - 126;
    s = max(0, min(16, s));
    const unsigned sw = __reduce_max_sync(0xFFFFFFFFu, (unsigned)s);

    // X = A * (t * 2^-sw), in place (exact exponent-field 2^-sw).
    const float scale = t * __uint_as_float((127u - sw) << 23);
    const u64 sc2 = pack2(scale, scale);
#pragma unroll
    for (int i = 0; i < 8; ++i) Xp[i] = mul2(Xp[i], sc2);

    // X2 = X*X ; X3 = X*X2 (row-pair form, broadcasts on the fly).
    u64 X2[8], X3[8];
    mm4p_rp(Xp, Xp, X2);
    mm4p_rp(Xp, X2, X3);

    // PS coefficient blocks.
    const float c2 = 1.0f / 2.0f;
    const float c3 = 1.0f / 6.0f,   c4 = 1.0f / 24.0f,   c5 = 1.0f / 120.0f;
    const float c6 = 1.0f / 720.0f, c7 = 1.0f / 5040.0f, c8 = 1.0f / 40320.0f;

    u64 B0[8], B1[8], B2[8];
#pragma unroll
    for (int i = 0; i < 4; ++i) {
#pragma unroll
        for (int jp = 0; jp < 2; ++jp) {
            const int p = i * 2 + jp;
            const bool dlo = (jp == (i >> 1)) && ((i & 1) == 0);
            const bool dhi = (jp == (i >> 1)) && ((i & 1) == 1);
            const u64 i1  = pack2(dlo ? 1.0f : 0.0f, dhi ? 1.0f : 0.0f);
            const u64 ic3 = pack2(dlo ? c3 : 0.0f,   dhi ? c3 : 0.0f);
            const u64 ic6 = pack2(dlo ? c6 : 0.0f,   dhi ? c6 : 0.0f);
            B0[p] = fma2(X2[p], pack2(c2, c2), add2(Xp[p], i1));
            B1[p] = fma2(X2[p], pack2(c5, c5), fma2(Xp[p], pack2(c4, c4), ic3));
            B2[p] = fma2(X2[p], pack2(c8, c8), fma2(Xp[p], pack2(c7, c7), ic6));
        }
    }

    // Horner in X^3:  T1 = X3*B2 + B1 ;  P = X3*T1 + B0
    u64 T1[8], P[8];
    mm4p_rp_acc(X3, B2, B1, T1);
    mm4p_rp_acc(X3, T1, B0, P);

    // Square sw times (warp-uniform trip count, broadcasts on the fly).
    for (unsigned q = 0; q < sw; ++q) {
        u64 C[8];
        mm4p_rp(P, P, C);
#pragma unroll
        for (int i = 0; i < 8; ++i) P[i] = C[i];
    }

    // Store with streaming hint (written once, never re-read).
    ulonglong2* op = reinterpret_cast<ulonglong2*>(out) + (size_t)idx * 4;
    __stcs(op + 0, make_ulonglong2(P[0], P[1]));
    __stcs(op + 1, make_ulonglong2(P[2], P[3]));
    __stcs(op + 2, make_ulonglong2(P[4], P[5]));
    __stcs(op + 3, make_ulonglong2(P[6], P[7]));
}

extern "C" void kernel_launch(void* const* d_in, const int* in_sizes, int n_in,
                              void* d_out, int out_size) {
    const float* rate = (const float*)d_in[0];
    const float* time = (const float*)d_in[1];
    float* out = (float*)d_out;

    expm44_kernel<<<NMAT / TPB, TPB>>>(rate, time, out);
}